// round 1
// baseline (speedup 1.0000x reference)
#include <cuda_runtime.h>
#include <cuda_bf16.h>
#include <math.h>

// ---------------- problem constants ----------------
constexpr int Bc  = 4;
constexpr int Tc  = 1024;
constexpr int Dc  = 512;
constexpr int Hc  = 8;
constexpr int Lc  = 6;
constexpr int Vc  = 128;
constexpr int DFFc = 2048;
constexpr int BT  = Bc * Tc;          // 4096
constexpr long TD  = (long)Tc * Dc;   // 524288
constexpr long TT  = (long)Tc * Tc;   // 1048576
constexpr long BTD = (long)Bc * Tc * Dc;

// ---------------- scratch (static device memory; no allocation) ----------------
__device__ __align__(256) float g_x[BT * Dc];                 // residual stream
__device__ __align__(256) float g_q[Hc * Bc * Tc * Dc];       // [H,B,T,D]
__device__ __align__(256) float g_k[Hc * Bc * Tc * Dc];
__device__ __align__(256) float g_v[Hc * Bc * Tc * Dc];
__device__ __align__(256) float g_scores[(long)Hc * Bc * Tc * Tc]; // [H*B,T,T]
__device__ __align__(256) float g_o[Hc * Bc * Tc * Dc];
__device__ __align__(256) float g_cat[BT * Hc * Dc];          // [BT, H*D]
__device__ __align__(256) float g_a[BT * Dc];
__device__ __align__(256) float g_h1[BT * DFFc];
__device__ __align__(256) float g_tmp[BT * Dc];
__device__ __align__(256) float g_rowloss[BT];

// ---------------- generic tiled fp32 GEMM ----------------
// C[M,N] = A[M,K] * B  (+bias, +relu), batched via z-strides.
// NT:      B is [N,K] row-major (B transposed)
// CAUSAL:  skip tiles entirely above the diagonal (scores GEMM)
// KLIM:    limit K loop to m0+BM (attn rows are zero beyond the diagonal)
template<bool NT, bool CAUSAL, bool KLIM, bool BIAS, bool RELU>
__global__ __launch_bounds__(256) void gemm128_kernel(
    const float* __restrict__ Ag, const float* __restrict__ Bg,
    const float* __restrict__ biasg, float* __restrict__ Cg,
    int M, int N, int K, long sA, long sB, long sBias, long sC)
{
    constexpr int BM = 128, BN = 128, BK = 8;
    const int m0 = blockIdx.y * BM;
    const int n0 = blockIdx.x * BN;
    if (CAUSAL && n0 >= m0 + BM) return;

    const int bz = blockIdx.z;
    const float* A  = Ag + (long)bz * sA;
    const float* Bp = Bg + (long)bz * sB;
    float*       C  = Cg + (long)bz * sC;

    int kend = K;
    if (KLIM) { int kl = m0 + BM; kend = kl < K ? kl : K; }

    __shared__ float As[BK][BM];
    __shared__ float Bs[BK][BN];

    const int tid  = threadIdx.x;
    const int tx   = tid & 15;        // 16 col groups of 8
    const int ty   = tid >> 4;        // 16 row groups of 8
    const int arow = tid >> 1;        // A/B(NT) load: row in tile
    const int aseg = (tid & 1) << 2;  // which float4 of the 8-wide k segment
    const int bkr  = tid >> 5;        // B(NN) load: k row
    const int bnc  = (tid & 31) << 2; // B(NN) load: n col (float4)

    float acc[8][8];
#pragma unroll
    for (int i = 0; i < 8; i++)
#pragma unroll
        for (int j = 0; j < 8; j++) acc[i][j] = 0.0f;

    for (int k0 = 0; k0 < kend; k0 += BK) {
        float4 av = *reinterpret_cast<const float4*>(A + (long)(m0 + arow) * K + k0 + aseg);
        As[aseg + 0][arow] = av.x; As[aseg + 1][arow] = av.y;
        As[aseg + 2][arow] = av.z; As[aseg + 3][arow] = av.w;
        if (NT) {
            float4 bv = *reinterpret_cast<const float4*>(Bp + (long)(n0 + arow) * K + k0 + aseg);
            Bs[aseg + 0][arow] = bv.x; Bs[aseg + 1][arow] = bv.y;
            Bs[aseg + 2][arow] = bv.z; Bs[aseg + 3][arow] = bv.w;
        } else {
            float4 bv = *reinterpret_cast<const float4*>(Bp + (long)(k0 + bkr) * N + n0 + bnc);
            *reinterpret_cast<float4*>(&Bs[bkr][bnc]) = bv;
        }
        __syncthreads();
#pragma unroll
        for (int kk = 0; kk < BK; kk++) {
            float a_[8], b_[8];
            *reinterpret_cast<float4*>(&a_[0]) = *reinterpret_cast<const float4*>(&As[kk][ty * 8]);
            *reinterpret_cast<float4*>(&a_[4]) = *reinterpret_cast<const float4*>(&As[kk][ty * 8 + 4]);
            *reinterpret_cast<float4*>(&b_[0]) = *reinterpret_cast<const float4*>(&Bs[kk][tx * 8]);
            *reinterpret_cast<float4*>(&b_[4]) = *reinterpret_cast<const float4*>(&Bs[kk][tx * 8 + 4]);
#pragma unroll
            for (int i = 0; i < 8; i++)
#pragma unroll
                for (int j = 0; j < 8; j++)
                    acc[i][j] += a_[i] * b_[j];
        }
        __syncthreads();
    }

    float bj[8];
    if (BIAS) {
        const float* bp = biasg + (long)bz * sBias + n0 + tx * 8;
#pragma unroll
        for (int j = 0; j < 8; j++) bj[j] = bp[j];
    }
#pragma unroll
    for (int i = 0; i < 8; i++) {
        long off = (long)(m0 + ty * 8 + i) * N + n0 + tx * 8;
        float v[8];
#pragma unroll
        for (int j = 0; j < 8; j++) {
            float t = acc[i][j];
            if (BIAS) t += bj[j];
            if (RELU) t = fmaxf(t, 0.0f);
            v[j] = t;
        }
        *reinterpret_cast<float4*>(C + off)     = make_float4(v[0], v[1], v[2], v[3]);
        *reinterpret_cast<float4*>(C + off + 4) = make_float4(v[4], v[5], v[6], v[7]);
    }
}

// ---------------- embedding gather ----------------
__global__ void embed_kernel(const int* __restrict__ tok, const float* __restrict__ emb,
                             float* __restrict__ x)
{
    int row = blockIdx.x;
    int tid = threadIdx.x;       // 256
    int t = tok[row];
    x[(long)row * Dc + tid]        = emb[(long)t * Dc + tid];
    x[(long)row * Dc + tid + 256]  = emb[(long)t * Dc + tid + 256];
}

// ---------------- causal softmax (in place), zero-fills s>t ----------------
__global__ void softmax_causal_kernel(float* __restrict__ S)
{
    long row = blockIdx.x;               // hb*T + t, 32768 rows
    int t = (int)(row & (Tc - 1));
    float* p = S + row * Tc;
    int tid = threadIdx.x;               // 256
    __shared__ float sh[256];

    float mx = -3.4e38f;
    for (int s = tid; s <= t; s += 256) mx = fmaxf(mx, p[s]);
    sh[tid] = mx; __syncthreads();
    for (int o = 128; o > 0; o >>= 1) { if (tid < o) sh[tid] = fmaxf(sh[tid], sh[tid + o]); __syncthreads(); }
    mx = sh[0]; __syncthreads();

    float sum = 0.0f;
    for (int s = tid; s <= t; s += 256) { float e = expf(p[s] - mx); p[s] = e; sum += e; }
    sh[tid] = sum; __syncthreads();
    for (int o = 128; o > 0; o >>= 1) { if (tid < o) sh[tid] += sh[tid + o]; __syncthreads(); }
    float inv = 1.0f / sh[0];

    for (int s = tid; s < Tc; s += 256) p[s] = (s <= t) ? p[s] * inv : 0.0f;
}

// ---------------- head concat: [H,B,T,D] -> [BT, H*D] (float4 copy) ----------------
__global__ void concat_kernel(const float* __restrict__ o, float* __restrict__ cat)
{
    long i = (long)blockIdx.x * 256 + threadIdx.x;   // float4 index; grid covers all
    int m  = (int)(i >> 10);          // /1024 float4 per out row (H*D/4)
    int f4 = (int)(i & 1023);
    int h  = f4 >> 7;                 // /128
    int e4 = f4 & 127;
    int bb = m >> 10;                 // /T
    int t  = m & 1023;
    const float4* src = reinterpret_cast<const float4*>(o);
    float4 v = src[((long)(h * Bc + bb) * Tc + t) * (Dc / 4) + e4];
    reinterpret_cast<float4*>(cat)[i] = v;
}

// ---------------- residual add + layernorm ----------------
__global__ void add_ln_kernel(const float* __restrict__ xin, const float* __restrict__ res,
                              const float* __restrict__ g, const float* __restrict__ b,
                              float* __restrict__ out)
{
    int row = blockIdx.x;
    int tid = threadIdx.x;           // 256, two elems each (D=512)
    long base = (long)row * Dc;
    float v0 = xin[base + tid], v1 = xin[base + tid + 256];
    if (res) { v0 += res[base + tid]; v1 += res[base + tid + 256]; }

    __shared__ float sh[256];
    sh[tid] = v0 + v1; __syncthreads();
    for (int o = 128; o > 0; o >>= 1) { if (tid < o) sh[tid] += sh[tid + o]; __syncthreads(); }
    float m = sh[0] * (1.0f / Dc); __syncthreads();

    float d0 = v0 - m, d1 = v1 - m;
    sh[tid] = d0 * d0 + d1 * d1; __syncthreads();
    for (int o = 128; o > 0; o >>= 1) { if (tid < o) sh[tid] += sh[tid + o]; __syncthreads(); }
    float inv = rsqrtf(sh[0] * (1.0f / Dc) + 1e-5f);

    out[base + tid]       = d0 * inv * g[tid]       + b[tid];
    out[base + tid + 256] = d1 * inv * g[tid + 256] + b[tid + 256];
}

// ---------------- per-row cross-entropy pieces ----------------
__global__ void row_loss_kernel(const float* __restrict__ logits, const int* __restrict__ labels,
                                float* __restrict__ rl)
{
    int r = blockIdx.x;
    int tid = threadIdx.x;           // 128 == V
    float v = logits[(long)r * Vc + tid];
    __shared__ float sh[128];
    sh[tid] = v; __syncthreads();
    for (int o = 64; o > 0; o >>= 1) { if (tid < o) sh[tid] = fmaxf(sh[tid], sh[tid + o]); __syncthreads(); }
    float mx = sh[0]; __syncthreads();
    sh[tid] = expf(v - mx); __syncthreads();
    for (int o = 64; o > 0; o >>= 1) { if (tid < o) sh[tid] += sh[tid + o]; __syncthreads(); }
    if (tid == 0) {
        float lse = mx + logf(sh[0]);
        rl[r] = lse - logits[(long)r * Vc + labels[r]];
    }
}

__global__ void final_loss_kernel(const float* __restrict__ rl, float* __restrict__ out)
{
    int tid = threadIdx.x;           // 256
    __shared__ float sh[256];
    float s = 0.0f;
    for (int i = tid; i < BT; i += 256) s += rl[i];
    sh[tid] = s; __syncthreads();
    for (int o = 128; o > 0; o >>= 1) { if (tid < o) sh[tid] += sh[tid + o]; __syncthreads(); }
    if (tid == 0) out[0] = sh[0] * (1.0f / BT);
}

// ---------------- host launch ----------------
extern "C" void kernel_launch(void* const* d_in, const int* in_sizes, int n_in,
                              void* d_out, int out_size)
{
    const int*   tokens = (const int*)d_in[0];
    const int*   labels = (const int*)d_in[1];
    const float* emb    = (const float*)d_in[2];
    const float* Wq     = (const float*)d_in[3];
    const float* bq     = (const float*)d_in[4];
    const float* Wk     = (const float*)d_in[5];
    const float* bk     = (const float*)d_in[6];
    const float* Wv     = (const float*)d_in[7];
    const float* bv     = (const float*)d_in[8];
    const float* Wo     = (const float*)d_in[9];
    const float* bo     = (const float*)d_in[10];
    const float* ln1_g  = (const float*)d_in[11];
    const float* ln1_b  = (const float*)d_in[12];
    const float* W1     = (const float*)d_in[13];
    const float* b1     = (const float*)d_in[14];
    const float* W2     = (const float*)d_in[15];
    const float* b2     = (const float*)d_in[16];
    const float* ln2_g  = (const float*)d_in[17];
    const float* ln2_b  = (const float*)d_in[18];
    const float* lnf_g  = (const float*)d_in[19];
    const float* lnf_b  = (const float*)d_in[20];
    const float* Wout   = (const float*)d_in[21];
    const float* bout   = (const float*)d_in[22];
    float* out = (float*)d_out;

    float *px, *pq, *pk, *pv, *ps, *po, *pcat, *pa, *ph1, *ptmp, *prl;
    cudaGetSymbolAddress((void**)&px,   g_x);
    cudaGetSymbolAddress((void**)&pq,   g_q);
    cudaGetSymbolAddress((void**)&pk,   g_k);
    cudaGetSymbolAddress((void**)&pv,   g_v);
    cudaGetSymbolAddress((void**)&ps,   g_scores);
    cudaGetSymbolAddress((void**)&po,   g_o);
    cudaGetSymbolAddress((void**)&pcat, g_cat);
    cudaGetSymbolAddress((void**)&pa,   g_a);
    cudaGetSymbolAddress((void**)&ph1,  g_h1);
    cudaGetSymbolAddress((void**)&ptmp, g_tmp);
    cudaGetSymbolAddress((void**)&prl,  g_rowloss);

    embed_kernel<<<BT, 256>>>(tokens, emb, px);

    const long WDD = (long)Dc * Dc;            // per-head weight stride
    for (int l = 0; l < Lc; l++) {
        const float* Wql = Wq + (long)l * Hc * WDD;
        const float* Wkl = Wk + (long)l * Hc * WDD;
        const float* Wvl = Wv + (long)l * Hc * WDD;

        // QKV: batched over heads. A = x (stride 0), C layout [H][BT,D]
        dim3 gqkv(Dc / 128, BT / 128, Hc);
        gemm128_kernel<false,false,false,true,false><<<gqkv, 256>>>(
            px, Wql, bq + (long)l * Hc * Dc, pq, BT, Dc, Dc, 0, WDD, Dc, BTD);
        gemm128_kernel<false,false,false,true,false><<<gqkv, 256>>>(
            px, Wkl, bk + (long)l * Hc * Dc, pk, BT, Dc, Dc, 0, WDD, Dc, BTD);
        gemm128_kernel<false,false,false,true,false><<<gqkv, 256>>>(
            px, Wvl, bv + (long)l * Hc * Dc, pv, BT, Dc, Dc, 0, WDD, Dc, BTD);

        // scores = q @ k^T  (batched over H*B, causal tile skip)
        dim3 gsc(Tc / 128, Tc / 128, Hc * Bc);
        gemm128_kernel<true,true,false,false,false><<<gsc, 256>>>(
            pq, pk, nullptr, ps, Tc, Tc, Dc, TD, TD, 0, TT);

        softmax_causal_kernel<<<Hc * Bc * Tc, 256>>>(ps);

        // o = attn @ v   (K loop limited by causality)
        dim3 gov(Dc / 128, Tc / 128, Hc * Bc);
        gemm128_kernel<false,false,true,false,false><<<gov, 256>>>(
            ps, pv, nullptr, po, Tc, Dc, Tc, TT, TD, 0, TD);

        // concat heads -> [BT, H*D]
        concat_kernel<<<(BT * Hc * Dc / 4) / 256, 256>>>(po, pcat);

        // a = cat @ Wo[l] + bo[l]
        dim3 gwo(Dc / 128, BT / 128, 1);
        gemm128_kernel<false,false,false,true,false><<<gwo, 256>>>(
            pcat, Wo + (long)l * Hc * Dc * Dc, bo + (long)l * Dc, pa,
            BT, Dc, Hc * Dc, 0, 0, 0, 0);

        add_ln_kernel<<<BT, 256>>>(px, pa, ln1_g + (long)l * Dc, ln1_b + (long)l * Dc, px);

        // MLP
        dim3 gm1(DFFc / 128, BT / 128, 1);
        gemm128_kernel<false,false,false,true,true><<<gm1, 256>>>(
            px, W1 + (long)l * Dc * DFFc, b1 + (long)l * DFFc, ph1,
            BT, DFFc, Dc, 0, 0, 0, 0);
        dim3 gm2(Dc / 128, BT / 128, 1);
        gemm128_kernel<false,false,false,true,false><<<gm2, 256>>>(
            ph1, W2 + (long)l * DFFc * Dc, b2 + (long)l * Dc, pa,
            BT, Dc, DFFc, 0, 0, 0, 0);

        add_ln_kernel<<<BT, 256>>>(px, pa, ln2_g + (long)l * Dc, ln2_b + (long)l * Dc, px);
    }

    // final LN + logits into d_out
    add_ln_kernel<<<BT, 256>>>(px, nullptr, lnf_g, lnf_b, ptmp);
    dim3 glog(Vc / 128, BT / 128, 1);
    gemm128_kernel<false,false,false,true,false><<<glog, 256>>>(
        ptmp, Wout, bout, out, BT, Vc, Dc, 0, 0, 0, 0);

    // loss -> last element of d_out
    row_loss_kernel<<<BT, 128>>>(out, labels, prl);
    final_loss_kernel<<<1, 256>>>(prl, out + (out_size - 1));
}

// round 3
// speedup vs baseline: 1.4309x; 1.4309x over previous
#include <cuda_runtime.h>
#include <cuda_bf16.h>
#include <math.h>

// ---------------- problem constants ----------------
constexpr int Bc  = 4;
constexpr int Tc  = 1024;
constexpr int Dc  = 512;
constexpr int Hc  = 8;
constexpr int Lc  = 6;
constexpr int Vc  = 128;
constexpr int DFFc = 2048;
constexpr int BT  = Bc * Tc;          // 4096
constexpr long TD  = (long)Tc * Dc;   // 524288
constexpr long TT  = (long)Tc * Tc;   // 1048576
constexpr long BTD = (long)Bc * Tc * Dc;

// ---------------- scratch (static device memory; no allocation) ----------------
__device__ __align__(256) float g_x[BT * Dc];                 // residual stream
__device__ __align__(256) float g_q[Hc * Bc * Tc * Dc];       // [H,B,T,D]
__device__ __align__(256) float g_k[Hc * Bc * Tc * Dc];
__device__ __align__(256) float g_v[Hc * Bc * Tc * Dc];
__device__ __align__(256) float g_scores[(long)Hc * Bc * Tc * Tc]; // [H*B,T,T]
__device__ __align__(256) float g_o[Hc * Bc * Tc * Dc];
__device__ __align__(256) float g_cat[BT * Hc * Dc];          // [BT, H*D]
__device__ __align__(256) float g_a[BT * Dc];
__device__ __align__(256) float g_h1[BT * DFFc];
__device__ __align__(256) float g_tmp[BT * Dc];
__device__ __align__(256) float g_rowloss[BT];

// ---------------- helpers ----------------
__device__ __forceinline__ void split_tf32(float x, unsigned& hi, unsigned& lo) {
    unsigned h;
    asm("cvt.rna.tf32.f32 %0, %1;" : "=r"(h) : "f"(x));
    float r = x - __uint_as_float(h);
    unsigned l;
    asm("cvt.rna.tf32.f32 %0, %1;" : "=r"(l) : "f"(r));
    hi = h; lo = l;
}

__device__ __forceinline__ void mma_tf32(float* c, const unsigned* a, const unsigned* b) {
    asm volatile(
        "mma.sync.aligned.m16n8k8.row.col.f32.tf32.tf32.f32 "
        "{%0,%1,%2,%3}, {%4,%5,%6,%7}, {%8,%9}, {%0,%1,%2,%3};\n"
        : "+f"(c[0]), "+f"(c[1]), "+f"(c[2]), "+f"(c[3])
        : "r"(a[0]), "r"(a[1]), "r"(a[2]), "r"(a[3]), "r"(b[0]), "r"(b[1]));
}

// ---------------- 3xTF32 tensor-core GEMM (fp32-accurate) ----------------
// C[M,N] = A[M,K] * B  (+bias, +relu), batched via z-strides.
// Operands split into hi+lo tf32; product = Ah*Bh + Al*Bh + Ah*Bl.
// NT:      B is [N,K] row-major (B transposed)
// CAUSAL:  skip tiles entirely above the diagonal (scores GEMM)
// KLIM:    limit K loop to m0+BM (attn rows are zero beyond the diagonal)
// CTA tile 128x128x32, 8 warps (2 m x 4 n), warp tile 64x32, mma m16n8k8.
constexpr int APAD = 36;   // row stride (words) for [128][36] layouts
constexpr int KPAD = 132;  // row stride (words) for [32][132] layout (NN B)
constexpr int TILE_WORDS = 128 * APAD;                 // 4608
constexpr int GEMM_SMEM_BYTES = 4 * TILE_WORDS * 4;    // 73728

template<bool NT, bool CAUSAL, bool KLIM, bool BIAS, bool RELU>
__global__ __launch_bounds__(256) void mma_gemm_kernel(
    const float* __restrict__ Ag, const float* __restrict__ Bg,
    const float* __restrict__ biasg, float* __restrict__ Cg,
    int M, int N, int K, long sA, long sB, long sBias, long sC)
{
    constexpr int BM = 128, BN = 128, BK = 32;

    const int m0 = blockIdx.y * BM;
    const int n0 = blockIdx.x * BN;
    if (CAUSAL && n0 >= m0 + BM) return;

    const int bz = blockIdx.z;
    const float* A  = Ag + (long)bz * sA;
    const float* Bp = Bg + (long)bz * sB;
    float*       C  = Cg + (long)bz * sC;

    int kend = K;
    if (KLIM) { int kl = m0 + BM; kend = kl < K ? kl : K; }

    extern __shared__ unsigned smem_u[];
    unsigned* Ash = smem_u;                       // [128][APAD]
    unsigned* Asl = smem_u + TILE_WORDS;
    unsigned* Bsh = smem_u + 2 * TILE_WORDS;      // NT: [n][APAD]; NN: [k][KPAD]
    unsigned* Bsl = smem_u + 3 * TILE_WORDS;

    const int tid  = threadIdx.x;
    const int wid  = tid >> 5;
    const int lane = tid & 31;
    const int warp_m = wid >> 2;   // 0..1  (64 rows each)
    const int warp_n = wid & 3;    // 0..3  (32 cols each)
    const int g = lane >> 2;       // 0..7
    const int c = lane & 3;        // 0..3

    float acc[4][4][4];
#pragma unroll
    for (int mi = 0; mi < 4; mi++)
#pragma unroll
        for (int ni = 0; ni < 4; ni++)
#pragma unroll
            for (int r = 0; r < 4; r++) acc[mi][ni][r] = 0.0f;

    const int arow = tid >> 3;        // 0..31 base rows per iter-chunk (A / NT-B loads)
    const int ac4  = tid & 7;         // float4 column within 32-wide K
    const int bkr  = tid >> 5;        // NN B: k row (0..7 per iter-chunk)
    const int bc4  = tid & 31;        // NN B: float4 col within 128-wide N

    for (int k0 = 0; k0 < kend; k0 += BK) {
        // ---- producer: A tile [128 x 32] -> hi/lo ----
#pragma unroll
        for (int it = 0; it < 4; it++) {
            int row = arow + it * 32;
            float4 v = *reinterpret_cast<const float4*>(A + (long)(m0 + row) * K + k0 + ac4 * 4);
            uint4 th, tl;
            split_tf32(v.x, th.x, tl.x); split_tf32(v.y, th.y, tl.y);
            split_tf32(v.z, th.z, tl.z); split_tf32(v.w, th.w, tl.w);
            *reinterpret_cast<uint4*>(&Ash[row * APAD + ac4 * 4]) = th;
            *reinterpret_cast<uint4*>(&Asl[row * APAD + ac4 * 4]) = tl;
        }
        // ---- producer: B tile -> hi/lo ----
        if (NT) {
#pragma unroll
            for (int it = 0; it < 4; it++) {
                int row = arow + it * 32;
                float4 v = *reinterpret_cast<const float4*>(Bp + (long)(n0 + row) * K + k0 + ac4 * 4);
                uint4 th, tl;
                split_tf32(v.x, th.x, tl.x); split_tf32(v.y, th.y, tl.y);
                split_tf32(v.z, th.z, tl.z); split_tf32(v.w, th.w, tl.w);
                *reinterpret_cast<uint4*>(&Bsh[row * APAD + ac4 * 4]) = th;
                *reinterpret_cast<uint4*>(&Bsl[row * APAD + ac4 * 4]) = tl;
            }
        } else {
#pragma unroll
            for (int it = 0; it < 4; it++) {
                int krow = bkr + it * 8;
                float4 v = *reinterpret_cast<const float4*>(Bp + (long)(k0 + krow) * N + n0 + bc4 * 4);
                uint4 th, tl;
                split_tf32(v.x, th.x, tl.x); split_tf32(v.y, th.y, tl.y);
                split_tf32(v.z, th.z, tl.z); split_tf32(v.w, th.w, tl.w);
                *reinterpret_cast<uint4*>(&Bsh[krow * KPAD + bc4 * 4]) = th;
                *reinterpret_cast<uint4*>(&Bsl[krow * KPAD + bc4 * 4]) = tl;
            }
        }
        __syncthreads();

        // ---- consumer: 4 k-steps of 8, 3 MMAs per fragment pair ----
#pragma unroll
        for (int ks = 0; ks < 4; ks++) {
            const int kk = ks * 8;
            unsigned afh[4][4], afl[4][4];
#pragma unroll
            for (int mi = 0; mi < 4; mi++) {
                int mb = warp_m * 64 + mi * 16 + g;
                afh[mi][0] = Ash[(mb    ) * APAD + kk + c    ];
                afh[mi][1] = Ash[(mb + 8) * APAD + kk + c    ];
                afh[mi][2] = Ash[(mb    ) * APAD + kk + c + 4];
                afh[mi][3] = Ash[(mb + 8) * APAD + kk + c + 4];
                afl[mi][0] = Asl[(mb    ) * APAD + kk + c    ];
                afl[mi][1] = Asl[(mb + 8) * APAD + kk + c    ];
                afl[mi][2] = Asl[(mb    ) * APAD + kk + c + 4];
                afl[mi][3] = Asl[(mb + 8) * APAD + kk + c + 4];
            }
            unsigned bfh[4][2], bfl[4][2];
#pragma unroll
            for (int ni = 0; ni < 4; ni++) {
                int nb = warp_n * 32 + ni * 8 + g;
                if (NT) {
                    bfh[ni][0] = Bsh[nb * APAD + kk + c    ];
                    bfh[ni][1] = Bsh[nb * APAD + kk + c + 4];
                    bfl[ni][0] = Bsl[nb * APAD + kk + c    ];
                    bfl[ni][1] = Bsl[nb * APAD + kk + c + 4];
                } else {
                    bfh[ni][0] = Bsh[(kk + c    ) * KPAD + nb];
                    bfh[ni][1] = Bsh[(kk + c + 4) * KPAD + nb];
                    bfl[ni][0] = Bsl[(kk + c    ) * KPAD + nb];
                    bfl[ni][1] = Bsl[(kk + c + 4) * KPAD + nb];
                }
            }
#pragma unroll
            for (int mi = 0; mi < 4; mi++)
#pragma unroll
                for (int ni = 0; ni < 4; ni++) {
                    mma_tf32(acc[mi][ni], afh[mi], bfh[ni]);
                    mma_tf32(acc[mi][ni], afl[mi], bfh[ni]);
                    mma_tf32(acc[mi][ni], afh[mi], bfl[ni]);
                }
        }
        __syncthreads();
    }

    // ---- epilogue ----
#pragma unroll
    for (int ni = 0; ni < 4; ni++) {
        int col = n0 + warp_n * 32 + ni * 8 + 2 * c;
        float b0 = 0.f, b1 = 0.f;
        if (BIAS) {
            const float* bp = biasg + (long)bz * sBias;
            b0 = bp[col]; b1 = bp[col + 1];
        }
#pragma unroll
        for (int mi = 0; mi < 4; mi++) {
            int row0 = m0 + warp_m * 64 + mi * 16 + g;
            int row1 = row0 + 8;
            float v0 = acc[mi][ni][0] + b0, v1 = acc[mi][ni][1] + b1;
            float v2 = acc[mi][ni][2] + b0, v3 = acc[mi][ni][3] + b1;
            if (RELU) {
                v0 = fmaxf(v0, 0.f); v1 = fmaxf(v1, 0.f);
                v2 = fmaxf(v2, 0.f); v3 = fmaxf(v3, 0.f);
            }
            *reinterpret_cast<float2*>(C + (long)row0 * N + col) = make_float2(v0, v1);
            *reinterpret_cast<float2*>(C + (long)row1 * N + col) = make_float2(v2, v3);
        }
    }
}

// ---------------- embedding gather ----------------
__global__ void embed_kernel(const int* __restrict__ tok, const float* __restrict__ emb,
                             float* __restrict__ x)
{
    int row = blockIdx.x;
    int tid = threadIdx.x;       // 256
    int t = tok[row];
    x[(long)row * Dc + tid]        = emb[(long)t * Dc + tid];
    x[(long)row * Dc + tid + 256]  = emb[(long)t * Dc + tid + 256];
}

// ---------------- causal softmax (in place), zero-fills s>t ----------------
__global__ void softmax_causal_kernel(float* __restrict__ S)
{
    long row = blockIdx.x;               // hb*T + t, 32768 rows
    int t = (int)(row & (Tc - 1));
    float* p = S + row * Tc;
    int tid = threadIdx.x;               // 256
    __shared__ float sh[256];

    float mx = -3.4e38f;
    for (int s = tid; s <= t; s += 256) mx = fmaxf(mx, p[s]);
    sh[tid] = mx; __syncthreads();
    for (int o = 128; o > 0; o >>= 1) { if (tid < o) sh[tid] = fmaxf(sh[tid], sh[tid + o]); __syncthreads(); }
    mx = sh[0]; __syncthreads();

    float sum = 0.0f;
    for (int s = tid; s <= t; s += 256) { float e = expf(p[s] - mx); p[s] = e; sum += e; }
    sh[tid] = sum; __syncthreads();
    for (int o = 128; o > 0; o >>= 1) { if (tid < o) sh[tid] += sh[tid + o]; __syncthreads(); }
    float inv = 1.0f / sh[0];

    for (int s = tid; s < Tc; s += 256) p[s] = (s <= t) ? p[s] * inv : 0.0f;
}

// ---------------- head concat: [H,B,T,D] -> [BT, H*D] (float4 copy) ----------------
__global__ void concat_kernel(const float* __restrict__ o, float* __restrict__ cat)
{
    long i = (long)blockIdx.x * 256 + threadIdx.x;   // float4 index; grid covers all
    int m  = (int)(i >> 10);          // /1024 float4 per out row (H*D/4)
    int f4 = (int)(i & 1023);
    int h  = f4 >> 7;                 // /128
    int e4 = f4 & 127;
    int bb = m >> 10;                 // /T
    int t  = m & 1023;
    const float4* src = reinterpret_cast<const float4*>(o);
    float4 v = src[((long)(h * Bc + bb) * Tc + t) * (Dc / 4) + e4];
    reinterpret_cast<float4*>(cat)[i] = v;
}

// ---------------- residual add + layernorm ----------------
__global__ void add_ln_kernel(const float* __restrict__ xin, const float* __restrict__ res,
                              const float* __restrict__ g, const float* __restrict__ b,
                              float* __restrict__ out)
{
    int row = blockIdx.x;
    int tid = threadIdx.x;           // 256, two elems each (D=512)
    long base = (long)row * Dc;
    float v0 = xin[base + tid], v1 = xin[base + tid + 256];
    if (res) { v0 += res[base + tid]; v1 += res[base + tid + 256]; }

    __shared__ float sh[256];
    sh[tid] = v0 + v1; __syncthreads();
    for (int o = 128; o > 0; o >>= 1) { if (tid < o) sh[tid] += sh[tid + o]; __syncthreads(); }
    float m = sh[0] * (1.0f / Dc); __syncthreads();

    float d0 = v0 - m, d1 = v1 - m;
    sh[tid] = d0 * d0 + d1 * d1; __syncthreads();
    for (int o = 128; o > 0; o >>= 1) { if (tid < o) sh[tid] += sh[tid + o]; __syncthreads(); }
    float inv = rsqrtf(sh[0] * (1.0f / Dc) + 1e-5f);

    out[base + tid]       = d0 * inv * g[tid]       + b[tid];
    out[base + tid + 256] = d1 * inv * g[tid + 256] + b[tid + 256];
}

// ---------------- per-row cross-entropy pieces ----------------
__global__ void row_loss_kernel(const float* __restrict__ logits, const int* __restrict__ labels,
                                float* __restrict__ rl)
{
    int r = blockIdx.x;
    int tid = threadIdx.x;           // 128 == V
    float v = logits[(long)r * Vc + tid];
    __shared__ float sh[128];
    sh[tid] = v; __syncthreads();
    for (int o = 64; o > 0; o >>= 1) { if (tid < o) sh[tid] = fmaxf(sh[tid], sh[tid + o]); __syncthreads(); }
    float mx = sh[0]; __syncthreads();
    sh[tid] = expf(v - mx); __syncthreads();
    for (int o = 64; o > 0; o >>= 1) { if (tid < o) sh[tid] += sh[tid + o]; __syncthreads(); }
    if (tid == 0) {
        float lse = mx + logf(sh[0]);
        rl[r] = lse - logits[(long)r * Vc + labels[r]];
    }
}

__global__ void final_loss_kernel(const float* __restrict__ rl, float* __restrict__ out)
{
    int tid = threadIdx.x;           // 256
    __shared__ float sh[256];
    float s = 0.0f;
    for (int i = tid; i < BT; i += 256) s += rl[i];
    sh[tid] = s; __syncthreads();
    for (int o = 128; o > 0; o >>= 1) { if (tid < o) sh[tid] += sh[tid + o]; __syncthreads(); }
    if (tid == 0) out[0] = sh[0] * (1.0f / BT);
}

// ---------------- host launch ----------------
extern "C" void kernel_launch(void* const* d_in, const int* in_sizes, int n_in,
                              void* d_out, int out_size)
{
    const int*   tokens = (const int*)d_in[0];
    const int*   labels = (const int*)d_in[1];
    const float* emb    = (const float*)d_in[2];
    const float* Wq     = (const float*)d_in[3];
    const float* bq     = (const float*)d_in[4];
    const float* Wk     = (const float*)d_in[5];
    const float* bk     = (const float*)d_in[6];
    const float* Wv     = (const float*)d_in[7];
    const float* bv     = (const float*)d_in[8];
    const float* Wo     = (const float*)d_in[9];
    const float* bo     = (const float*)d_in[10];
    const float* ln1_g  = (const float*)d_in[11];
    const float* ln1_b  = (const float*)d_in[12];
    const float* W1     = (const float*)d_in[13];
    const float* b1     = (const float*)d_in[14];
    const float* W2     = (const float*)d_in[15];
    const float* b2     = (const float*)d_in[16];
    const float* ln2_g  = (const float*)d_in[17];
    const float* ln2_b  = (const float*)d_in[18];
    const float* lnf_g  = (const float*)d_in[19];
    const float* lnf_b  = (const float*)d_in[20];
    const float* Wout   = (const float*)d_in[21];
    const float* bout   = (const float*)d_in[22];
    float* out = (float*)d_out;

    float *px, *pq, *pk, *pv, *ps, *po, *pcat, *pa, *ph1, *ptmp, *prl;
    cudaGetSymbolAddress((void**)&px,   g_x);
    cudaGetSymbolAddress((void**)&pq,   g_q);
    cudaGetSymbolAddress((void**)&pk,   g_k);
    cudaGetSymbolAddress((void**)&pv,   g_v);
    cudaGetSymbolAddress((void**)&ps,   g_scores);
    cudaGetSymbolAddress((void**)&po,   g_o);
    cudaGetSymbolAddress((void**)&pcat, g_cat);
    cudaGetSymbolAddress((void**)&pa,   g_a);
    cudaGetSymbolAddress((void**)&ph1,  g_h1);
    cudaGetSymbolAddress((void**)&ptmp, g_tmp);
    cudaGetSymbolAddress((void**)&prl,  g_rowloss);

    // allow 72KB dynamic smem for each GEMM instantiation (idempotent)
    cudaFuncSetAttribute(mma_gemm_kernel<false,false,false,true,false>,
                         cudaFuncAttributeMaxDynamicSharedMemorySize, GEMM_SMEM_BYTES);
    cudaFuncSetAttribute(mma_gemm_kernel<true,true,false,false,false>,
                         cudaFuncAttributeMaxDynamicSharedMemorySize, GEMM_SMEM_BYTES);
    cudaFuncSetAttribute(mma_gemm_kernel<false,false,true,false,false>,
                         cudaFuncAttributeMaxDynamicSharedMemorySize, GEMM_SMEM_BYTES);
    cudaFuncSetAttribute(mma_gemm_kernel<false,false,false,true,true>,
                         cudaFuncAttributeMaxDynamicSharedMemorySize, GEMM_SMEM_BYTES);

    embed_kernel<<<BT, 256>>>(tokens, emb, px);

    const long WDD = (long)Dc * Dc;            // per-head weight stride
    for (int l = 0; l < Lc; l++) {
        const float* Wql = Wq + (long)l * Hc * WDD;
        const float* Wkl = Wk + (long)l * Hc * WDD;
        const float* Wvl = Wv + (long)l * Hc * WDD;

        // QKV: batched over heads. A = x (stride 0), C layout [H][BT,D]
        dim3 gqkv(Dc / 128, BT / 128, Hc);
        mma_gemm_kernel<false,false,false,true,false><<<gqkv, 256, GEMM_SMEM_BYTES>>>(
            px, Wql, bq + (long)l * Hc * Dc, pq, BT, Dc, Dc, 0, WDD, Dc, BTD);
        mma_gemm_kernel<false,false,false,true,false><<<gqkv, 256, GEMM_SMEM_BYTES>>>(
            px, Wkl, bk + (long)l * Hc * Dc, pk, BT, Dc, Dc, 0, WDD, Dc, BTD);
        mma_gemm_kernel<false,false,false,true,false><<<gqkv, 256, GEMM_SMEM_BYTES>>>(
            px, Wvl, bv + (long)l * Hc * Dc, pv, BT, Dc, Dc, 0, WDD, Dc, BTD);

        // scores = q @ k^T  (batched over H*B, causal tile skip)
        dim3 gsc(Tc / 128, Tc / 128, Hc * Bc);
        mma_gemm_kernel<true,true,false,false,false><<<gsc, 256, GEMM_SMEM_BYTES>>>(
            pq, pk, nullptr, ps, Tc, Tc, Dc, TD, TD, 0, TT);

        softmax_causal_kernel<<<Hc * Bc * Tc, 256>>>(ps);

        // o = attn @ v   (K loop limited by causality)
        dim3 gov(Dc / 128, Tc / 128, Hc * Bc);
        mma_gemm_kernel<false,false,true,false,false><<<gov, 256, GEMM_SMEM_BYTES>>>(
            ps, pv, nullptr, po, Tc, Dc, Tc, TT, TD, 0, TD);

        // concat heads -> [BT, H*D]
        concat_kernel<<<(BT * Hc * Dc / 4) / 256, 256>>>(po, pcat);

        // a = cat @ Wo[l] + bo[l]
        dim3 gwo(Dc / 128, BT / 128, 1);
        mma_gemm_kernel<false,false,false,true,false><<<gwo, 256, GEMM_SMEM_BYTES>>>(
            pcat, Wo + (long)l * Hc * Dc * Dc, bo + (long)l * Dc, pa,
            BT, Dc, Hc * Dc, 0, 0, 0, 0);

        add_ln_kernel<<<BT, 256>>>(px, pa, ln1_g + (long)l * Dc, ln1_b + (long)l * Dc, px);

        // MLP
        dim3 gm1(DFFc / 128, BT / 128, 1);
        mma_gemm_kernel<false,false,false,true,true><<<gm1, 256, GEMM_SMEM_BYTES>>>(
            px, W1 + (long)l * Dc * DFFc, b1 + (long)l * DFFc, ph1,
            BT, DFFc, Dc, 0, 0, 0, 0);
        dim3 gm2(Dc / 128, BT / 128, 1);
        mma_gemm_kernel<false,false,false,true,false><<<gm2, 256, GEMM_SMEM_BYTES>>>(
            ph1, W2 + (long)l * DFFc * Dc, b2 + (long)l * Dc, pa,
            BT, Dc, DFFc, 0, 0, 0, 0);

        add_ln_kernel<<<BT, 256>>>(px, pa, ln2_g + (long)l * Dc, ln2_b + (long)l * Dc, px);
    }

    // final LN + logits into d_out
    add_ln_kernel<<<BT, 256>>>(px, nullptr, lnf_g, lnf_b, ptmp);
    dim3 glog(Vc / 128, BT / 128, 1);
    mma_gemm_kernel<false,false,false,true,false><<<glog, 256, GEMM_SMEM_BYTES>>>(
        ptmp, Wout, bout, out, BT, Vc, Dc, 0, 0, 0, 0);

    // loss -> last element of d_out
    row_loss_kernel<<<BT, 128>>>(out, labels, prl);
    final_loss_kernel<<<1, 256>>>(prl, out + (out_size - 1));
}

// round 4
// speedup vs baseline: 2.0970x; 1.4656x over previous
#include <cuda_runtime.h>
#include <cuda_bf16.h>
#include <math.h>

// ---------------- problem constants ----------------
constexpr int Bc  = 4;
constexpr int Tc  = 1024;
constexpr int Dc  = 512;
constexpr int Hc  = 8;
constexpr int Lc  = 6;
constexpr int Vc  = 128;
constexpr int DFFc = 2048;
constexpr int BT  = Bc * Tc;          // 4096
constexpr long TD  = (long)Tc * Dc;   // 524288
constexpr long TT  = (long)Tc * Tc;   // 1048576
constexpr long BTD = (long)Bc * Tc * Dc;

// ---------------- scratch (static device memory; no allocation) ----------------
__device__ __align__(256) float g_x[BT * Dc];                 // residual stream
__device__ __align__(256) float g_q[Hc * Bc * Tc * Dc];       // [H,B,T,D]
__device__ __align__(256) float g_k[Hc * Bc * Tc * Dc];
__device__ __align__(256) float g_v[Hc * Bc * Tc * Dc];
__device__ __align__(256) float g_scores[(long)Hc * Bc * Tc * Tc]; // [H*B,T,T]
__device__ __align__(256) float g_o[Hc * Bc * Tc * Dc];
__device__ __align__(256) float g_cat[BT * Hc * Dc];          // [BT, H*D]
__device__ __align__(256) float g_a[BT * Dc];
__device__ __align__(256) float g_h1[BT * DFFc];
__device__ __align__(256) float g_tmp[BT * Dc];
__device__ __align__(256) float g_rowloss[BT];

// ---------------- helpers ----------------
// split fp32 -> bf16 hi + bf16 lo (x ~= hi + lo, residual ~2^-18 |x|)
__device__ __forceinline__ void split_bf16(float x, unsigned short& h, unsigned short& l) {
    __nv_bfloat16 hb = __float2bfloat16_rn(x);
    __nv_bfloat16 lb = __float2bfloat16_rn(x - __bfloat162float(hb));
    h = __bfloat16_as_ushort(hb);
    l = __bfloat16_as_ushort(lb);
}

__device__ __forceinline__ void split4(float4 v, uint2& hi, uint2& lo) {
    unsigned short hx, hy, hz, hw, lx, ly, lz, lw;
    split_bf16(v.x, hx, lx); split_bf16(v.y, hy, ly);
    split_bf16(v.z, hz, lz); split_bf16(v.w, hw, lw);
    hi.x = (unsigned)hx | ((unsigned)hy << 16);
    hi.y = (unsigned)hz | ((unsigned)hw << 16);
    lo.x = (unsigned)lx | ((unsigned)ly << 16);
    lo.y = (unsigned)lz | ((unsigned)lw << 16);
}

__device__ __forceinline__ void mma_bf16(float* c, const unsigned* a, const unsigned* b) {
    asm volatile(
        "mma.sync.aligned.m16n8k16.row.col.f32.bf16.bf16.f32 "
        "{%0,%1,%2,%3}, {%4,%5,%6,%7}, {%8,%9}, {%0,%1,%2,%3};\n"
        : "+f"(c[0]), "+f"(c[1]), "+f"(c[2]), "+f"(c[3])
        : "r"(a[0]), "r"(a[1]), "r"(a[2]), "r"(a[3]), "r"(b[0]), "r"(b[1]));
}

__device__ __forceinline__ unsigned lds32(const unsigned short* p) {
    return *reinterpret_cast<const unsigned*>(p);
}

// ---------------- 3xBF16 split tensor-core GEMM (fp32-class accuracy) ----------------
// C[M,N] = A[M,K] * B  (+bias, +relu), batched via z-strides.
// Operands split into hi+lo bf16; product = Ah*Bh + Al*Bh + Ah*Bl.
// NT:      B is [N,K] row-major (B transposed).  NN: B is [K,N]; producer transposes
//          into the same [n][k] smem layout, so the consumer is identical.
// CAUSAL:  skip tiles entirely above the diagonal (scores GEMM)
// KLIM:    limit K loop to m0+BM (attn rows are zero beyond the diagonal)
// CTA tile 128x128x32, 8 warps (2 m x 4 n), warp tile 64x32, mma m16n8k16.
// Register prefetch: next K-tile gmem loads overlap current tile's MMAs.
constexpr int KP = 40;   // smem row stride in bf16 elements (32 + 8 pad) -> conflict-free

template<bool NT, bool CAUSAL, bool KLIM, bool BIAS, bool RELU>
__global__ __launch_bounds__(256) void mma_gemm_kernel(
    const float* __restrict__ Ag, const float* __restrict__ Bg,
    const float* __restrict__ biasg, float* __restrict__ Cg,
    int M, int N, int K, long sA, long sB, long sBias, long sC)
{
    constexpr int BM = 128, BN = 128, BK = 32;

    const int m0 = blockIdx.y * BM;
    const int n0 = blockIdx.x * BN;
    if (CAUSAL && n0 >= m0 + BM) return;

    const int bz = blockIdx.z;
    const float* A  = Ag + (long)bz * sA;
    const float* Bp = Bg + (long)bz * sB;
    float*       C  = Cg + (long)bz * sC;

    int kend = K;
    if (KLIM) { int kl = m0 + BM; kend = kl < K ? kl : K; }

    __shared__ unsigned short Ash[128 * KP];
    __shared__ unsigned short Asl[128 * KP];
    __shared__ unsigned short Bsh[128 * KP];   // [n][k] for both NT and NN
    __shared__ unsigned short Bsl[128 * KP];

    const int tid  = threadIdx.x;
    const int wid  = tid >> 5;
    const int lane = tid & 31;
    const int warp_m = wid >> 2;   // 0..1  (64 rows each)
    const int warp_n = wid & 3;    // 0..3  (32 cols each)
    const int g = lane >> 2;       // 0..7
    const int c = lane & 3;        // 0..3

    float acc[4][4][4];
#pragma unroll
    for (int mi = 0; mi < 4; mi++)
#pragma unroll
        for (int ni = 0; ni < 4; ni++)
#pragma unroll
            for (int r = 0; r < 4; r++) acc[mi][ni][r] = 0.0f;

    // producer index maps
    const int arow = tid >> 3;        // 0..31 (A / NT-B rows per chunk, x4 chunks)
    const int ac4  = tid & 7;         // float4 column within 32-wide K
    const int nIdx = tid & 127;       // NN B: n within tile
    const int kq   = tid >> 7;        // NN B: 0..1 (k quad select)

    // prefetch registers
    float4 pa[4];
    float4 pb_nt[4];
    float  pb_nn[4][4];

    // ---- prologue: load first tile into registers ----
    {
        const int kcur = 0;
#pragma unroll
        for (int it = 0; it < 4; it++) {
            int row = arow + it * 32;
            pa[it] = *reinterpret_cast<const float4*>(A + (long)(m0 + row) * K + kcur + ac4 * 4);
        }
        if (NT) {
#pragma unroll
            for (int it = 0; it < 4; it++) {
                int row = arow + it * 32;
                pb_nt[it] = *reinterpret_cast<const float4*>(Bp + (long)(n0 + row) * K + kcur + ac4 * 4);
            }
        } else {
#pragma unroll
            for (int it = 0; it < 4; it++) {
                int kb = it * 8 + kq * 4;
#pragma unroll
                for (int r = 0; r < 4; r++)
                    pb_nn[it][r] = Bp[(long)(kcur + kb + r) * N + n0 + nIdx];
            }
        }
    }

    for (int k0 = 0; k0 < kend; k0 += BK) {
        // ---- store prefetched tile to smem (with bf16 hi/lo split) ----
#pragma unroll
        for (int it = 0; it < 4; it++) {
            int row = arow + it * 32;
            uint2 h, l;
            split4(pa[it], h, l);
            *reinterpret_cast<uint2*>(&Ash[row * KP + ac4 * 4]) = h;
            *reinterpret_cast<uint2*>(&Asl[row * KP + ac4 * 4]) = l;
        }
        if (NT) {
#pragma unroll
            for (int it = 0; it < 4; it++) {
                int row = arow + it * 32;
                uint2 h, l;
                split4(pb_nt[it], h, l);
                *reinterpret_cast<uint2*>(&Bsh[row * KP + ac4 * 4]) = h;
                *reinterpret_cast<uint2*>(&Bsl[row * KP + ac4 * 4]) = l;
            }
        } else {
#pragma unroll
            for (int it = 0; it < 4; it++) {
                int kb = it * 8 + kq * 4;
                float4 v = make_float4(pb_nn[it][0], pb_nn[it][1], pb_nn[it][2], pb_nn[it][3]);
                uint2 h, l;
                split4(v, h, l);
                *reinterpret_cast<uint2*>(&Bsh[nIdx * KP + kb]) = h;
                *reinterpret_cast<uint2*>(&Bsl[nIdx * KP + kb]) = l;
            }
        }
        __syncthreads();

        // ---- issue next tile's gmem loads (overlap with MMA below) ----
        const int k1 = k0 + BK;
        if (k1 < kend) {
#pragma unroll
            for (int it = 0; it < 4; it++) {
                int row = arow + it * 32;
                pa[it] = *reinterpret_cast<const float4*>(A + (long)(m0 + row) * K + k1 + ac4 * 4);
            }
            if (NT) {
#pragma unroll
                for (int it = 0; it < 4; it++) {
                    int row = arow + it * 32;
                    pb_nt[it] = *reinterpret_cast<const float4*>(Bp + (long)(n0 + row) * K + k1 + ac4 * 4);
                }
            } else {
#pragma unroll
                for (int it = 0; it < 4; it++) {
                    int kb = it * 8 + kq * 4;
#pragma unroll
                    for (int r = 0; r < 4; r++)
                        pb_nn[it][r] = Bp[(long)(k1 + kb + r) * N + n0 + nIdx];
                }
            }
        }

        // ---- consume: 2 k-steps of 16, 3 MMAs per fragment pair ----
#pragma unroll
        for (int ks = 0; ks < 2; ks++) {
            const int kk = ks * 16;
            unsigned afh[4][4], afl[4][4];
#pragma unroll
            for (int mi = 0; mi < 4; mi++) {
                int mb = warp_m * 64 + mi * 16 + g;
                int b0 = mb * KP + kk + 2 * c;
                int b1 = (mb + 8) * KP + kk + 2 * c;
                afh[mi][0] = lds32(&Ash[b0]);     afh[mi][1] = lds32(&Ash[b1]);
                afh[mi][2] = lds32(&Ash[b0 + 8]); afh[mi][3] = lds32(&Ash[b1 + 8]);
                afl[mi][0] = lds32(&Asl[b0]);     afl[mi][1] = lds32(&Asl[b1]);
                afl[mi][2] = lds32(&Asl[b0 + 8]); afl[mi][3] = lds32(&Asl[b1 + 8]);
            }
            unsigned bfh[4][2], bfl[4][2];
#pragma unroll
            for (int ni = 0; ni < 4; ni++) {
                int nb = warp_n * 32 + ni * 8 + g;
                int b0 = nb * KP + kk + 2 * c;
                bfh[ni][0] = lds32(&Bsh[b0]); bfh[ni][1] = lds32(&Bsh[b0 + 8]);
                bfl[ni][0] = lds32(&Bsl[b0]); bfl[ni][1] = lds32(&Bsl[b0 + 8]);
            }
#pragma unroll
            for (int mi = 0; mi < 4; mi++)
#pragma unroll
                for (int ni = 0; ni < 4; ni++) {
                    mma_bf16(acc[mi][ni], afh[mi], bfh[ni]);
                    mma_bf16(acc[mi][ni], afl[mi], bfh[ni]);
                    mma_bf16(acc[mi][ni], afh[mi], bfl[ni]);
                }
        }
        __syncthreads();
    }

    // ---- epilogue ----
#pragma unroll
    for (int ni = 0; ni < 4; ni++) {
        int col = n0 + warp_n * 32 + ni * 8 + 2 * c;
        float b0 = 0.f, b1 = 0.f;
        if (BIAS) {
            const float* bp = biasg + (long)bz * sBias;
            b0 = bp[col]; b1 = bp[col + 1];
        }
#pragma unroll
        for (int mi = 0; mi < 4; mi++) {
            int row0 = m0 + warp_m * 64 + mi * 16 + g;
            int row1 = row0 + 8;
            float v0 = acc[mi][ni][0] + b0, v1 = acc[mi][ni][1] + b1;
            float v2 = acc[mi][ni][2] + b0, v3 = acc[mi][ni][3] + b1;
            if (RELU) {
                v0 = fmaxf(v0, 0.f); v1 = fmaxf(v1, 0.f);
                v2 = fmaxf(v2, 0.f); v3 = fmaxf(v3, 0.f);
            }
            *reinterpret_cast<float2*>(C + (long)row0 * N + col) = make_float2(v0, v1);
            *reinterpret_cast<float2*>(C + (long)row1 * N + col) = make_float2(v2, v3);
        }
    }
}

// ---------------- embedding gather ----------------
__global__ void embed_kernel(const int* __restrict__ tok, const float* __restrict__ emb,
                             float* __restrict__ x)
{
    int row = blockIdx.x;
    int tid = threadIdx.x;       // 256
    int t = tok[row];
    x[(long)row * Dc + tid]        = emb[(long)t * Dc + tid];
    x[(long)row * Dc + tid + 256]  = emb[(long)t * Dc + tid + 256];
}

// ---------------- causal softmax (in place), zero-fills s>t ----------------
__global__ void softmax_causal_kernel(float* __restrict__ S)
{
    long row = blockIdx.x;               // hb*T + t, 32768 rows
    int t = (int)(row & (Tc - 1));
    float* p = S + row * Tc;
    int tid = threadIdx.x;               // 256
    __shared__ float sh[256];

    float mx = -3.4e38f;
    for (int s = tid; s <= t; s += 256) mx = fmaxf(mx, p[s]);
    sh[tid] = mx; __syncthreads();
    for (int o = 128; o > 0; o >>= 1) { if (tid < o) sh[tid] = fmaxf(sh[tid], sh[tid + o]); __syncthreads(); }
    mx = sh[0]; __syncthreads();

    float sum = 0.0f;
    for (int s = tid; s <= t; s += 256) { float e = expf(p[s] - mx); p[s] = e; sum += e; }
    sh[tid] = sum; __syncthreads();
    for (int o = 128; o > 0; o >>= 1) { if (tid < o) sh[tid] += sh[tid + o]; __syncthreads(); }
    float inv = 1.0f / sh[0];

    for (int s = tid; s < Tc; s += 256) p[s] = (s <= t) ? p[s] * inv : 0.0f;
}

// ---------------- head concat: [H,B,T,D] -> [BT, H*D] (float4 copy) ----------------
__global__ void concat_kernel(const float* __restrict__ o, float* __restrict__ cat)
{
    long i = (long)blockIdx.x * 256 + threadIdx.x;   // float4 index; grid covers all
    int m  = (int)(i >> 10);          // /1024 float4 per out row (H*D/4)
    int f4 = (int)(i & 1023);
    int h  = f4 >> 7;                 // /128
    int e4 = f4 & 127;
    int bb = m >> 10;                 // /T
    int t  = m & 1023;
    const float4* src = reinterpret_cast<const float4*>(o);
    float4 v = src[((long)(h * Bc + bb) * Tc + t) * (Dc / 4) + e4];
    reinterpret_cast<float4*>(cat)[i] = v;
}

// ---------------- residual add + layernorm ----------------
__global__ void add_ln_kernel(const float* __restrict__ xin, const float* __restrict__ res,
                              const float* __restrict__ g, const float* __restrict__ b,
                              float* __restrict__ out)
{
    int row = blockIdx.x;
    int tid = threadIdx.x;           // 256, two elems each (D=512)
    long base = (long)row * Dc;
    float v0 = xin[base + tid], v1 = xin[base + tid + 256];
    if (res) { v0 += res[base + tid]; v1 += res[base + tid + 256]; }

    __shared__ float sh[256];
    sh[tid] = v0 + v1; __syncthreads();
    for (int o = 128; o > 0; o >>= 1) { if (tid < o) sh[tid] += sh[tid + o]; __syncthreads(); }
    float m = sh[0] * (1.0f / Dc); __syncthreads();

    float d0 = v0 - m, d1 = v1 - m;
    sh[tid] = d0 * d0 + d1 * d1; __syncthreads();
    for (int o = 128; o > 0; o >>= 1) { if (tid < o) sh[tid] += sh[tid + o]; __syncthreads(); }
    float inv = rsqrtf(sh[0] * (1.0f / Dc) + 1e-5f);

    out[base + tid]       = d0 * inv * g[tid]       + b[tid];
    out[base + tid + 256] = d1 * inv * g[tid + 256] + b[tid + 256];
}

// ---------------- per-row cross-entropy pieces ----------------
__global__ void row_loss_kernel(const float* __restrict__ logits, const int* __restrict__ labels,
                                float* __restrict__ rl)
{
    int r = blockIdx.x;
    int tid = threadIdx.x;           // 128 == V
    float v = logits[(long)r * Vc + tid];
    __shared__ float sh[128];
    sh[tid] = v; __syncthreads();
    for (int o = 64; o > 0; o >>= 1) { if (tid < o) sh[tid] = fmaxf(sh[tid], sh[tid + o]); __syncthreads(); }
    float mx = sh[0]; __syncthreads();
    sh[tid] = expf(v - mx); __syncthreads();
    for (int o = 64; o > 0; o >>= 1) { if (tid < o) sh[tid] += sh[tid + o]; __syncthreads(); }
    if (tid == 0) {
        float lse = mx + logf(sh[0]);
        rl[r] = lse - logits[(long)r * Vc + labels[r]];
    }
}

__global__ void final_loss_kernel(const float* __restrict__ rl, float* __restrict__ out)
{
    int tid = threadIdx.x;           // 256
    __shared__ float sh[256];
    float s = 0.0f;
    for (int i = tid; i < BT; i += 256) s += rl[i];
    sh[tid] = s; __syncthreads();
    for (int o = 128; o > 0; o >>= 1) { if (tid < o) sh[tid] += sh[tid + o]; __syncthreads(); }
    if (tid == 0) out[0] = sh[0] * (1.0f / BT);
}

// ---------------- host launch ----------------
extern "C" void kernel_launch(void* const* d_in, const int* in_sizes, int n_in,
                              void* d_out, int out_size)
{
    const int*   tokens = (const int*)d_in[0];
    const int*   labels = (const int*)d_in[1];
    const float* emb    = (const float*)d_in[2];
    const float* Wq     = (const float*)d_in[3];
    const float* bq     = (const float*)d_in[4];
    const float* Wk     = (const float*)d_in[5];
    const float* bk     = (const float*)d_in[6];
    const float* Wv     = (const float*)d_in[7];
    const float* bv     = (const float*)d_in[8];
    const float* Wo     = (const float*)d_in[9];
    const float* bo     = (const float*)d_in[10];
    const float* ln1_g  = (const float*)d_in[11];
    const float* ln1_b  = (const float*)d_in[12];
    const float* W1     = (const float*)d_in[13];
    const float* b1     = (const float*)d_in[14];
    const float* W2     = (const float*)d_in[15];
    const float* b2     = (const float*)d_in[16];
    const float* ln2_g  = (const float*)d_in[17];
    const float* ln2_b  = (const float*)d_in[18];
    const float* lnf_g  = (const float*)d_in[19];
    const float* lnf_b  = (const float*)d_in[20];
    const float* Wout   = (const float*)d_in[21];
    const float* bout   = (const float*)d_in[22];
    float* out = (float*)d_out;

    float *px, *pq, *pk, *pv, *ps, *po, *pcat, *pa, *ph1, *ptmp, *prl;
    cudaGetSymbolAddress((void**)&px,   g_x);
    cudaGetSymbolAddress((void**)&pq,   g_q);
    cudaGetSymbolAddress((void**)&pk,   g_k);
    cudaGetSymbolAddress((void**)&pv,   g_v);
    cudaGetSymbolAddress((void**)&ps,   g_scores);
    cudaGetSymbolAddress((void**)&po,   g_o);
    cudaGetSymbolAddress((void**)&pcat, g_cat);
    cudaGetSymbolAddress((void**)&pa,   g_a);
    cudaGetSymbolAddress((void**)&ph1,  g_h1);
    cudaGetSymbolAddress((void**)&ptmp, g_tmp);
    cudaGetSymbolAddress((void**)&prl,  g_rowloss);

    embed_kernel<<<BT, 256>>>(tokens, emb, px);

    const long WDD = (long)Dc * Dc;            // per-head weight stride
    for (int l = 0; l < Lc; l++) {
        const float* Wql = Wq + (long)l * Hc * WDD;
        const float* Wkl = Wk + (long)l * Hc * WDD;
        const float* Wvl = Wv + (long)l * Hc * WDD;

        // QKV: batched over heads. A = x (stride 0), C layout [H][BT,D]
        dim3 gqkv(Dc / 128, BT / 128, Hc);
        mma_gemm_kernel<false,false,false,true,false><<<gqkv, 256>>>(
            px, Wql, bq + (long)l * Hc * Dc, pq, BT, Dc, Dc, 0, WDD, Dc, BTD);
        mma_gemm_kernel<false,false,false,true,false><<<gqkv, 256>>>(
            px, Wkl, bk + (long)l * Hc * Dc, pk, BT, Dc, Dc, 0, WDD, Dc, BTD);
        mma_gemm_kernel<false,false,false,true,false><<<gqkv, 256>>>(
            px, Wvl, bv + (long)l * Hc * Dc, pv, BT, Dc, Dc, 0, WDD, Dc, BTD);

        // scores = q @ k^T  (batched over H*B, causal tile skip)
        dim3 gsc(Tc / 128, Tc / 128, Hc * Bc);
        mma_gemm_kernel<true,true,false,false,false><<<gsc, 256>>>(
            pq, pk, nullptr, ps, Tc, Tc, Dc, TD, TD, 0, TT);

        softmax_causal_kernel<<<Hc * Bc * Tc, 256>>>(ps);

        // o = attn @ v   (K loop limited by causality)
        dim3 gov(Dc / 128, Tc / 128, Hc * Bc);
        mma_gemm_kernel<false,false,true,false,false><<<gov, 256>>>(
            ps, pv, nullptr, po, Tc, Dc, Tc, TT, TD, 0, TD);

        // concat heads -> [BT, H*D]
        concat_kernel<<<(BT * Hc * Dc / 4) / 256, 256>>>(po, pcat);

        // a = cat @ Wo[l] + bo[l]
        dim3 gwo(Dc / 128, BT / 128, 1);
        mma_gemm_kernel<false,false,false,true,false><<<gwo, 256>>>(
            pcat, Wo + (long)l * Hc * Dc * Dc, bo + (long)l * Dc, pa,
            BT, Dc, Hc * Dc, 0, 0, 0, 0);

        add_ln_kernel<<<BT, 256>>>(px, pa, ln1_g + (long)l * Dc, ln1_b + (long)l * Dc, px);

        // MLP
        dim3 gm1(DFFc / 128, BT / 128, 1);
        mma_gemm_kernel<false,false,false,true,true><<<gm1, 256>>>(
            px, W1 + (long)l * Dc * DFFc, b1 + (long)l * DFFc, ph1,
            BT, DFFc, Dc, 0, 0, 0, 0);
        dim3 gm2(Dc / 128, BT / 128, 1);
        mma_gemm_kernel<false,false,false,true,false><<<gm2, 256>>>(
            ph1, W2 + (long)l * DFFc * Dc, b2 + (long)l * Dc, pa,
            BT, Dc, DFFc, 0, 0, 0, 0);

        add_ln_kernel<<<BT, 256>>>(px, pa, ln2_g + (long)l * Dc, ln2_b + (long)l * Dc, px);
    }

    // final LN + logits into d_out
    add_ln_kernel<<<BT, 256>>>(px, nullptr, lnf_g, lnf_b, ptmp);
    dim3 glog(Vc / 128, BT / 128, 1);
    mma_gemm_kernel<false,false,false,true,false><<<glog, 256>>>(
        ptmp, Wout, bout, out, BT, Vc, Dc, 0, 0, 0, 0);

    // loss -> last element of d_out
    row_loss_kernel<<<BT, 128>>>(out, labels, prl);
    final_loss_kernel<<<1, 256>>>(prl, out + (out_size - 1));
}

// round 5
// speedup vs baseline: 2.2797x; 1.0871x over previous
#include <cuda_runtime.h>
#include <cuda_bf16.h>
#include <math.h>

// ---------------- problem constants ----------------
constexpr int Bc  = 4;
constexpr int Tc  = 1024;
constexpr int Dc  = 512;
constexpr int Hc  = 8;
constexpr int Lc  = 6;
constexpr int Vc  = 128;
constexpr int DFFc = 2048;
constexpr int BT  = Bc * Tc;          // 4096
constexpr long TD  = (long)Tc * Dc;   // 524288
constexpr long TT  = (long)Tc * Tc;   // 1048576
constexpr long BTD = (long)Bc * Tc * Dc;
constexpr long HBTD = (long)Hc * BTD;
constexpr long HBTT = (long)Hc * Bc * TT;

typedef unsigned short u16;
typedef unsigned int   u32;

// ---------------- scratch (static device memory; no allocation) ----------------
__device__ __align__(256) float g_x[BT * Dc];          // residual stream (fp32)
__device__ __align__(256) float g_a[BT * Dc];          // attn/mlp branch output (fp32)
__device__ __align__(256) float g_rowloss[BT];

// split activations (bf16 hi/lo)
__device__ __align__(256) u16 g_xh[BT * Dc],   g_xl[BT * Dc];
__device__ __align__(256) u16 g_qh[HBTD],      g_ql[HBTD];       // [H,B,T,D]
__device__ __align__(256) u16 g_kh[HBTD],      g_kl[HBTD];       // [H,B,T,D]
__device__ __align__(256) u16 g_vth[HBTD],     g_vtl[HBTD];      // [H,B,D,T] (transposed)
__device__ __align__(256) u16 g_sh_[HBTT],     g_sl_[HBTT];      // scores/attn [H*B,T,T]
__device__ __align__(256) u16 g_oh[HBTD],      g_ol[HBTD];       // [H,B,T,D]
__device__ __align__(256) u16 g_cath[HBTD],    g_catl[HBTD];     // [BT, H*D]
__device__ __align__(256) u16 g_h1h[BT * DFFc], g_h1l[BT * DFFc];
__device__ __align__(256) u16 g_tmph[BT * Dc], g_tmpl[BT * Dc];

// split transposed weights  (B operand layout: [n][k] k-major)
__device__ __align__(256) u16 g_wqh[Lc*Hc*Dc*Dc], g_wql[Lc*Hc*Dc*Dc];
__device__ __align__(256) u16 g_wkh[Lc*Hc*Dc*Dc], g_wkl[Lc*Hc*Dc*Dc];
__device__ __align__(256) u16 g_wvh[Lc*Hc*Dc*Dc], g_wvl[Lc*Hc*Dc*Dc];
__device__ __align__(256) u16 g_woh[Lc*Hc*Dc*Dc], g_wol[Lc*Hc*Dc*Dc];  // [L][Dc][H*Dc]
__device__ __align__(256) u16 g_w1h[Lc*DFFc*Dc],  g_w1l[Lc*DFFc*Dc];   // [L][DFF][Dc]
__device__ __align__(256) u16 g_w2h[Lc*Dc*DFFc],  g_w2l[Lc*Dc*DFFc];   // [L][Dc][DFF]
__device__ __align__(256) u16 g_wouth[Vc*Dc],     g_woutl[Vc*Dc];      // [V][Dc]

// ---------------- helpers ----------------
__device__ __forceinline__ float bf2f(u16 u) { return __bfloat162float(__ushort_as_bfloat16(u)); }
__device__ __forceinline__ u16   f2bf(float f) { return __bfloat16_as_ushort(__float2bfloat16_rn(f)); }
__device__ __forceinline__ void  fsplit(float v, u16& h, u16& l) {
    h = f2bf(v);
    l = f2bf(v - bf2f(h));
}

__device__ __forceinline__ void mma_bf16(float* c, const u32* a, const u32* b) {
    asm volatile(
        "mma.sync.aligned.m16n8k16.row.col.f32.bf16.bf16.f32 "
        "{%0,%1,%2,%3}, {%4,%5,%6,%7}, {%8,%9}, {%0,%1,%2,%3};\n"
        : "+f"(c[0]), "+f"(c[1]), "+f"(c[2]), "+f"(c[3])
        : "r"(a[0]), "r"(a[1]), "r"(a[2]), "r"(a[3]), "r"(b[0]), "r"(b[1]));
}

__device__ __forceinline__ u32 lds32(const u16* p) { return *reinterpret_cast<const u32*>(p); }

__device__ __forceinline__ void cpasync16(u16* s, const u16* g) {
    u32 sa = (u32)__cvta_generic_to_shared(s);
    asm volatile("cp.async.cg.shared.global [%0], [%1], 16;\n" :: "r"(sa), "l"(g) : "memory");
}
__device__ __forceinline__ void cp_commit() {
    asm volatile("cp.async.commit_group;\n" ::: "memory");
}

// ---------------- 3xBF16-split tensor-core GEMM, cp.async 2-stage pipeline ----------------
// C[M,N] = A[M,K] * B^T  where A (hi/lo) is [M][K] k-major and B (hi/lo) is [N][K] k-major.
// Product = Ah*Bh + Al*Bh + Ah*Bl  (fp32-class accuracy, fp32 accumulate).
// CAUSAL: skip tiles above the diagonal.  KLIM: limit K to m0+BM (causal attn rows).
// OMODE: 0 = fp32 out (+bias/relu), 1 = split bf16 out, 2 = split out transposed for V
//        (writes [H,B,D,T] so attn@V is NT too).
// CTA tile 128x128x32, 8 warps (2m x 4n), warp tile 64x32, mma m16n8k16.
constexpr int KP = 40;                    // smem row stride (bf16): 80B, 16B-aligned, conflict-free
constexpr int TILE_E = 128 * KP;          // 5120 elements = 10240 B
constexpr int GEMM_SMEM = 8 * TILE_E * 2; // 4 arrays x 2 stages = 81920 B

template<bool CAUSAL, bool KLIM, bool BIAS, bool RELU, int OMODE>
__global__ __launch_bounds__(256) void gemm_bf3_kernel(
    const u16* __restrict__ Ahg, const u16* __restrict__ Alg,
    const u16* __restrict__ Bhg, const u16* __restrict__ Blg,
    const float* __restrict__ biasg,
    float* __restrict__ Cfg, u16* __restrict__ Chg, u16* __restrict__ Clg,
    int M, int N, int K, long sA, long sB, long sBias, long sC)
{
    constexpr int BM = 128, BK = 32;

    const int m0 = blockIdx.y * BM;
    const int n0 = blockIdx.x * 128;
    if (CAUSAL && n0 >= m0 + BM) return;

    const int bz = blockIdx.z;
    const u16* Ah = Ahg + (long)bz * sA;
    const u16* Al = Alg + (long)bz * sA;
    const u16* Bh = Bhg + (long)bz * sB;
    const u16* Bl = Blg + (long)bz * sB;

    int kend = K;
    if (KLIM) { int kl = m0 + BM; kend = kl < K ? kl : K; }

    extern __shared__ u16 sm[];

    const int tid  = threadIdx.x;
    const int wid  = tid >> 5;
    const int lane = tid & 31;
    const int warp_m = wid >> 2;
    const int warp_n = wid & 3;
    const int g = lane >> 2;
    const int c = lane & 3;

    // producer map: each thread does 2 16B chunks per array
    const int prow = tid >> 1;            // 0..127
    const int pcb  = (tid & 1) * 2;       // chunk base (8-bf16 chunks)

    auto issue_tile = [&](int kt, int buf) {
        const int k0 = kt * BK;
        const long abase = (long)(m0 + prow) * K + k0;
        const long bbase = (long)(n0 + prow) * K + k0;
        u16* s0 = sm + (buf * 4 + 0) * TILE_E;
        u16* s1 = sm + (buf * 4 + 1) * TILE_E;
        u16* s2 = sm + (buf * 4 + 2) * TILE_E;
        u16* s3 = sm + (buf * 4 + 3) * TILE_E;
#pragma unroll
        for (int cc = 0; cc < 2; cc++) {
            const int off = prow * KP + (pcb + cc) * 8;
            const int go  = (pcb + cc) * 8;
            cpasync16(s0 + off, Ah + abase + go);
            cpasync16(s1 + off, Al + abase + go);
            cpasync16(s2 + off, Bh + bbase + go);
            cpasync16(s3 + off, Bl + bbase + go);
        }
    };

    float acc[4][4][4];
#pragma unroll
    for (int mi = 0; mi < 4; mi++)
#pragma unroll
        for (int ni = 0; ni < 4; ni++)
#pragma unroll
            for (int r = 0; r < 4; r++) acc[mi][ni][r] = 0.0f;

    const int nt = kend / BK;
    issue_tile(0, 0);
    cp_commit();

    for (int i = 0; i < nt; i++) {
        const int buf = i & 1;
        if (i + 1 < nt) {
            issue_tile(i + 1, buf ^ 1);
            cp_commit();
            asm volatile("cp.async.wait_group 1;\n" ::: "memory");
        } else {
            asm volatile("cp.async.wait_group 0;\n" ::: "memory");
        }
        __syncthreads();

        const u16* Ash = sm + (buf * 4 + 0) * TILE_E;
        const u16* Asl = sm + (buf * 4 + 1) * TILE_E;
        const u16* Bsh = sm + (buf * 4 + 2) * TILE_E;
        const u16* Bsl = sm + (buf * 4 + 3) * TILE_E;

#pragma unroll
        for (int ks = 0; ks < 2; ks++) {
            const int kk = ks * 16;
            u32 afh[4][4], afl[4][4];
#pragma unroll
            for (int mi = 0; mi < 4; mi++) {
                const int mb = warp_m * 64 + mi * 16 + g;
                const int b0 = mb * KP + kk + 2 * c;
                const int b1 = (mb + 8) * KP + kk + 2 * c;
                afh[mi][0] = lds32(Ash + b0);     afh[mi][1] = lds32(Ash + b1);
                afh[mi][2] = lds32(Ash + b0 + 8); afh[mi][3] = lds32(Ash + b1 + 8);
                afl[mi][0] = lds32(Asl + b0);     afl[mi][1] = lds32(Asl + b1);
                afl[mi][2] = lds32(Asl + b0 + 8); afl[mi][3] = lds32(Asl + b1 + 8);
            }
            u32 bfh[4][2], bfl[4][2];
#pragma unroll
            for (int ni = 0; ni < 4; ni++) {
                const int nb = warp_n * 32 + ni * 8 + g;
                const int b0 = nb * KP + kk + 2 * c;
                bfh[ni][0] = lds32(Bsh + b0); bfh[ni][1] = lds32(Bsh + b0 + 8);
                bfl[ni][0] = lds32(Bsl + b0); bfl[ni][1] = lds32(Bsl + b0 + 8);
            }
#pragma unroll
            for (int mi = 0; mi < 4; mi++)
#pragma unroll
                for (int ni = 0; ni < 4; ni++) {
                    mma_bf16(acc[mi][ni], afh[mi], bfh[ni]);
                    mma_bf16(acc[mi][ni], afl[mi], bfh[ni]);
                    mma_bf16(acc[mi][ni], afh[mi], bfl[ni]);
                }
        }
        __syncthreads();
    }

    // ---- epilogue ----
    float* Cf = (OMODE == 0) ? Cfg + (long)bz * sC : nullptr;
    u16*   Ch = (OMODE != 0) ? Chg + (long)bz * ((OMODE == 2) ? 0 : sC) : nullptr;
    u16*   Cl = (OMODE != 0) ? Clg + (long)bz * ((OMODE == 2) ? 0 : sC) : nullptr;

#pragma unroll
    for (int ni = 0; ni < 4; ni++) {
        const int col = n0 + warp_n * 32 + ni * 8 + 2 * c;
        float bv0 = 0.f, bv1 = 0.f;
        if (BIAS) {
            const float* bp = biasg + (long)bz * sBias;
            bv0 = bp[col]; bv1 = bp[col + 1];
        }
#pragma unroll
        for (int mi = 0; mi < 4; mi++) {
            const int row0 = m0 + warp_m * 64 + mi * 16 + g;
            const int row1 = row0 + 8;
            float v0 = acc[mi][ni][0] + bv0, v1 = acc[mi][ni][1] + bv1;
            float v2 = acc[mi][ni][2] + bv0, v3 = acc[mi][ni][3] + bv1;
            if (RELU) {
                v0 = fmaxf(v0, 0.f); v1 = fmaxf(v1, 0.f);
                v2 = fmaxf(v2, 0.f); v3 = fmaxf(v3, 0.f);
            }
            if (OMODE == 0) {
                *reinterpret_cast<float2*>(Cf + (long)row0 * N + col) = make_float2(v0, v1);
                *reinterpret_cast<float2*>(Cf + (long)row1 * N + col) = make_float2(v2, v3);
            } else if (OMODE == 1) {
                u16 h0, l0, h1, l1;
                fsplit(v0, h0, l0); fsplit(v1, h1, l1);
                *reinterpret_cast<u32*>(Ch + (long)row0 * N + col) = (u32)h0 | ((u32)h1 << 16);
                *reinterpret_cast<u32*>(Cl + (long)row0 * N + col) = (u32)l0 | ((u32)l1 << 16);
                fsplit(v2, h0, l0); fsplit(v3, h1, l1);
                *reinterpret_cast<u32*>(Ch + (long)row1 * N + col) = (u32)h0 | ((u32)h1 << 16);
                *reinterpret_cast<u32*>(Cl + (long)row1 * N + col) = (u32)l0 | ((u32)l1 << 16);
            } else {
                // transposed V output: [H,B,D,T]; bz = head
                const int bb0 = row0 >> 10, t0 = row0 & 1023;
                const int bb1 = row1 >> 10, t1 = row1 & 1023;
                u16 h, l;
                long i0 = (((long)(bz * Bc + bb0)) * Dc + col) * Tc + t0;
                fsplit(v0, h, l); Ch[i0] = h;      Cl[i0] = l;
                fsplit(v1, h, l); Ch[i0 + Tc] = h; Cl[i0 + Tc] = l;
                long i1 = (((long)(bz * Bc + bb1)) * Dc + col) * Tc + t1;
                fsplit(v2, h, l); Ch[i1] = h;      Cl[i1] = l;
                fsplit(v3, h, l); Ch[i1 + Tc] = h; Cl[i1 + Tc] = l;
            }
        }
    }
}

// ---------------- weight convert + transpose:  W[b][K][N] fp32 -> Wh/Wl[b][N][K] bf16 ----------------
__global__ void convt_kernel(const float* __restrict__ W, u16* __restrict__ Wh,
                             u16* __restrict__ Wl, int K, int N)
{
    __shared__ float ts[32][33];
    const int b  = blockIdx.z;
    const int n0 = blockIdx.x * 32;
    const int k0 = blockIdx.y * 32;
    const float* Wb = W + (long)b * K * N;
    const int tx = threadIdx.x, ty = threadIdx.y;
#pragma unroll
    for (int i = ty; i < 32; i += 8)
        ts[i][tx] = Wb[(long)(k0 + i) * N + n0 + tx];
    __syncthreads();
#pragma unroll
    for (int i = ty; i < 32; i += 8) {
        float v = ts[tx][i];                      // = W[k0+tx][n0+i]
        u16 h, l; fsplit(v, h, l);
        long o = (long)b * N * K + (long)(n0 + i) * K + k0 + tx;
        Wh[o] = h; Wl[o] = l;
    }
}

// ---------------- embedding gather (fp32 + split) ----------------
__global__ void embed_kernel(const int* __restrict__ tok, const float* __restrict__ emb,
                             float* __restrict__ x, u16* __restrict__ xh, u16* __restrict__ xl)
{
    const int row = blockIdx.x;
    const int tid = threadIdx.x;    // 256
    const int t = tok[row];
    const long base = (long)row * Dc;
    float v0 = emb[(long)t * Dc + tid];
    float v1 = emb[(long)t * Dc + tid + 256];
    x[base + tid] = v0; x[base + tid + 256] = v1;
    u16 h, l;
    fsplit(v0, h, l); xh[base + tid] = h;       xl[base + tid] = l;
    fsplit(v1, h, l); xh[base + tid + 256] = h; xl[base + tid + 256] = l;
}

// ---------------- causal softmax on split arrays (in place), zero-fills s>t ----------------
__global__ void softmax_causal_kernel(u16* __restrict__ Sh, u16* __restrict__ Sl)
{
    const long row = blockIdx.x;              // hb*T + t
    const int t = (int)(row & (Tc - 1));
    u16* ph = Sh + row * Tc;
    u16* pl = Sl + row * Tc;
    const int tid = threadIdx.x;              // 256
    __shared__ float sh[256];

    float mx = -3.4e38f;
    for (int s = tid; s <= t; s += 256) mx = fmaxf(mx, bf2f(ph[s]) + bf2f(pl[s]));
    sh[tid] = mx; __syncthreads();
    for (int o = 128; o > 0; o >>= 1) { if (tid < o) sh[tid] = fmaxf(sh[tid], sh[tid + o]); __syncthreads(); }
    mx = sh[0]; __syncthreads();

    float sum = 0.0f;
    for (int s = tid; s <= t; s += 256) {
        float e = expf(bf2f(ph[s]) + bf2f(pl[s]) - mx);
        u16 h, l; fsplit(e, h, l);
        ph[s] = h; pl[s] = l;
        sum += e;
    }
    sh[tid] = sum; __syncthreads();
    for (int o = 128; o > 0; o >>= 1) { if (tid < o) sh[tid] += sh[tid + o]; __syncthreads(); }
    const float inv = 1.0f / sh[0];

    for (int s = tid; s < Tc; s += 256) {
        if (s <= t) {
            float v = (bf2f(ph[s]) + bf2f(pl[s])) * inv;
            u16 h, l; fsplit(v, h, l);
            ph[s] = h; pl[s] = l;
        } else { ph[s] = 0; pl[s] = 0; }
    }
}

// ---------------- head concat on split arrays: [H,B,T,D] -> [BT, H*D] ----------------
__global__ void concat_kernel(const u16* __restrict__ oh, const u16* __restrict__ ol,
                              u16* __restrict__ cath, u16* __restrict__ catl)
{
    const long i = (long)blockIdx.x * 256 + threadIdx.x;   // 4-bf16 group index
    const int m  = (int)(i >> 10);
    const int f4 = (int)(i & 1023);
    const int h  = f4 >> 7;
    const int e4 = f4 & 127;
    const int bb = m >> 10;
    const int t  = m & 1023;
    const long src = ((long)(h * Bc + bb) * Tc + t) * (Dc / 4) + e4;
    reinterpret_cast<uint2*>(cath)[i] = reinterpret_cast<const uint2*>(oh)[src];
    reinterpret_cast<uint2*>(catl)[i] = reinterpret_cast<const uint2*>(ol)[src];
}

// ---------------- residual add + layernorm (fp32 out + split out) ----------------
__global__ void add_ln_kernel(const float* __restrict__ xin, const float* __restrict__ res,
                              const float* __restrict__ g, const float* __restrict__ b,
                              float* __restrict__ out, u16* __restrict__ outh, u16* __restrict__ outl)
{
    const int row = blockIdx.x;
    const int tid = threadIdx.x;           // 256
    const long base = (long)row * Dc;
    float v0 = xin[base + tid], v1 = xin[base + tid + 256];
    if (res) { v0 += res[base + tid]; v1 += res[base + tid + 256]; }

    __shared__ float sh[256];
    sh[tid] = v0 + v1; __syncthreads();
    for (int o = 128; o > 0; o >>= 1) { if (tid < o) sh[tid] += sh[tid + o]; __syncthreads(); }
    const float m = sh[0] * (1.0f / Dc); __syncthreads();

    const float d0 = v0 - m, d1 = v1 - m;
    sh[tid] = d0 * d0 + d1 * d1; __syncthreads();
    for (int o = 128; o > 0; o >>= 1) { if (tid < o) sh[tid] += sh[tid + o]; __syncthreads(); }
    const float inv = rsqrtf(sh[0] * (1.0f / Dc) + 1e-5f);

    const float r0 = d0 * inv * g[tid]       + b[tid];
    const float r1 = d1 * inv * g[tid + 256] + b[tid + 256];
    out[base + tid] = r0; out[base + tid + 256] = r1;
    u16 h, l;
    fsplit(r0, h, l); outh[base + tid] = h;       outl[base + tid] = l;
    fsplit(r1, h, l); outh[base + tid + 256] = h; outl[base + tid + 256] = l;
}

// ---------------- per-row cross-entropy pieces ----------------
__global__ void row_loss_kernel(const float* __restrict__ logits, const int* __restrict__ labels,
                                float* __restrict__ rl)
{
    const int r = blockIdx.x;
    const int tid = threadIdx.x;           // 128 == V
    const float v = logits[(long)r * Vc + tid];
    __shared__ float sh[128];
    sh[tid] = v; __syncthreads();
    for (int o = 64; o > 0; o >>= 1) { if (tid < o) sh[tid] = fmaxf(sh[tid], sh[tid + o]); __syncthreads(); }
    const float mx = sh[0]; __syncthreads();
    sh[tid] = expf(v - mx); __syncthreads();
    for (int o = 64; o > 0; o >>= 1) { if (tid < o) sh[tid] += sh[tid + o]; __syncthreads(); }
    if (tid == 0) {
        const float lse = mx + logf(sh[0]);
        rl[r] = lse - logits[(long)r * Vc + labels[r]];
    }
}

__global__ void final_loss_kernel(const float* __restrict__ rl, float* __restrict__ out)
{
    const int tid = threadIdx.x;           // 256
    __shared__ float sh[256];
    float s = 0.0f;
    for (int i = tid; i < BT; i += 256) s += rl[i];
    sh[tid] = s; __syncthreads();
    for (int o = 128; o > 0; o >>= 1) { if (tid < o) sh[tid] += sh[tid + o]; __syncthreads(); }
    if (tid == 0) out[0] = sh[0] * (1.0f / BT);
}

// ---------------- host launch ----------------
#define SYM(p, s) cudaGetSymbolAddress((void**)&(p), s)

extern "C" void kernel_launch(void* const* d_in, const int* in_sizes, int n_in,
                              void* d_out, int out_size)
{
    const int*   tokens = (const int*)d_in[0];
    const int*   labels = (const int*)d_in[1];
    const float* emb    = (const float*)d_in[2];
    const float* Wq     = (const float*)d_in[3];
    const float* bq     = (const float*)d_in[4];
    const float* Wk     = (const float*)d_in[5];
    const float* bk     = (const float*)d_in[6];
    const float* Wv     = (const float*)d_in[7];
    const float* bv     = (const float*)d_in[8];
    const float* Wo     = (const float*)d_in[9];
    const float* bo     = (const float*)d_in[10];
    const float* ln1_g  = (const float*)d_in[11];
    const float* ln1_b  = (const float*)d_in[12];
    const float* W1     = (const float*)d_in[13];
    const float* b1     = (const float*)d_in[14];
    const float* W2     = (const float*)d_in[15];
    const float* b2     = (const float*)d_in[16];
    const float* ln2_g  = (const float*)d_in[17];
    const float* ln2_b  = (const float*)d_in[18];
    const float* lnf_g  = (const float*)d_in[19];
    const float* lnf_b  = (const float*)d_in[20];
    const float* Wout   = (const float*)d_in[21];
    const float* bout   = (const float*)d_in[22];
    float* out = (float*)d_out;

    float *px, *pa, *prl;
    u16 *pxh, *pxl, *pqh, *pql, *pkh, *pkl, *pvth, *pvtl, *psh, *psl;
    u16 *poh, *pol, *pcath, *pcatl, *ph1h, *ph1l, *ptmph, *ptmpl;
    u16 *pwqh, *pwql, *pwkh, *pwkl, *pwvh, *pwvl, *pwoh, *pwol;
    u16 *pw1h, *pw1l, *pw2h, *pw2l, *pwouth, *pwoutl;

    SYM(px, g_x); SYM(pa, g_a); SYM(prl, g_rowloss);
    SYM(pxh, g_xh); SYM(pxl, g_xl);
    SYM(pqh, g_qh); SYM(pql, g_ql); SYM(pkh, g_kh); SYM(pkl, g_kl);
    SYM(pvth, g_vth); SYM(pvtl, g_vtl);
    SYM(psh, g_sh_); SYM(psl, g_sl_);
    SYM(poh, g_oh); SYM(pol, g_ol);
    SYM(pcath, g_cath); SYM(pcatl, g_catl);
    SYM(ph1h, g_h1h); SYM(ph1l, g_h1l);
    SYM(ptmph, g_tmph); SYM(ptmpl, g_tmpl);
    SYM(pwqh, g_wqh); SYM(pwql, g_wql);
    SYM(pwkh, g_wkh); SYM(pwkl, g_wkl);
    SYM(pwvh, g_wvh); SYM(pwvl, g_wvl);
    SYM(pwoh, g_woh); SYM(pwol, g_wol);
    SYM(pw1h, g_w1h); SYM(pw1l, g_w1l);
    SYM(pw2h, g_w2h); SYM(pw2l, g_w2l);
    SYM(pwouth, g_wouth); SYM(pwoutl, g_woutl);

    // smem opt-in for all GEMM instantiations
    cudaFuncSetAttribute(gemm_bf3_kernel<false,false,true,false,1>,
                         cudaFuncAttributeMaxDynamicSharedMemorySize, GEMM_SMEM);
    cudaFuncSetAttribute(gemm_bf3_kernel<false,false,true,false,2>,
                         cudaFuncAttributeMaxDynamicSharedMemorySize, GEMM_SMEM);
    cudaFuncSetAttribute(gemm_bf3_kernel<true,false,false,false,1>,
                         cudaFuncAttributeMaxDynamicSharedMemorySize, GEMM_SMEM);
    cudaFuncSetAttribute(gemm_bf3_kernel<false,true,false,false,1>,
                         cudaFuncAttributeMaxDynamicSharedMemorySize, GEMM_SMEM);
    cudaFuncSetAttribute(gemm_bf3_kernel<false,false,true,false,0>,
                         cudaFuncAttributeMaxDynamicSharedMemorySize, GEMM_SMEM);
    cudaFuncSetAttribute(gemm_bf3_kernel<false,false,true,true,1>,
                         cudaFuncAttributeMaxDynamicSharedMemorySize, GEMM_SMEM);

    // ---- weight convert + transpose (per replay) ----
    dim3 cb(32, 8);
    convt_kernel<<<dim3(Dc/32, Dc/32, Lc*Hc), cb>>>(Wq, pwqh, pwql, Dc, Dc);
    convt_kernel<<<dim3(Dc/32, Dc/32, Lc*Hc), cb>>>(Wk, pwkh, pwkl, Dc, Dc);
    convt_kernel<<<dim3(Dc/32, Dc/32, Lc*Hc), cb>>>(Wv, pwvh, pwvl, Dc, Dc);
    convt_kernel<<<dim3(Dc/32, (Hc*Dc)/32, Lc), cb>>>(Wo, pwoh, pwol, Hc*Dc, Dc);
    convt_kernel<<<dim3(DFFc/32, Dc/32, Lc), cb>>>(W1, pw1h, pw1l, Dc, DFFc);
    convt_kernel<<<dim3(Dc/32, DFFc/32, Lc), cb>>>(W2, pw2h, pw2l, DFFc, Dc);
    convt_kernel<<<dim3(Vc/32, Dc/32, 1), cb>>>(Wout, pwouth, pwoutl, Dc, Vc);

    embed_kernel<<<BT, 256>>>(tokens, emb, px, pxh, pxl);

    const long WDD = (long)Dc * Dc;
    for (int l = 0; l < Lc; l++) {
        const long wofs = (long)l * Hc * WDD;

        // QKV (batched over heads; A = x, sA = 0)
        dim3 gqkv(Dc/128, BT/128, Hc);
        gemm_bf3_kernel<false,false,true,false,1><<<gqkv, 256, GEMM_SMEM>>>(
            pxh, pxl, pwqh + wofs, pwql + wofs, bq + (long)l*Hc*Dc,
            nullptr, pqh, pql, BT, Dc, Dc, 0, WDD, Dc, BTD);
        gemm_bf3_kernel<false,false,true,false,1><<<gqkv, 256, GEMM_SMEM>>>(
            pxh, pxl, pwkh + wofs, pwkl + wofs, bk + (long)l*Hc*Dc,
            nullptr, pkh, pkl, BT, Dc, Dc, 0, WDD, Dc, BTD);
        gemm_bf3_kernel<false,false,true,false,2><<<gqkv, 256, GEMM_SMEM>>>(
            pxh, pxl, pwvh + wofs, pwvl + wofs, bv + (long)l*Hc*Dc,
            nullptr, pvth, pvtl, BT, Dc, Dc, 0, WDD, Dc, 0);

        // scores = q @ k^T  (z = H*B, causal tile skip), split out
        dim3 gsc(Tc/128, Tc/128, Hc*Bc);
        gemm_bf3_kernel<true,false,false,false,1><<<gsc, 256, GEMM_SMEM>>>(
            pqh, pql, pkh, pkl, nullptr,
            nullptr, psh, psl, Tc, Tc, Dc, TD, TD, 0, TT);

        softmax_causal_kernel<<<Hc*Bc*Tc, 256>>>(psh, psl);

        // o = attn @ v  (B = vT [H,B,D,T], NT; K limited by causality)
        dim3 gov(Dc/128, Tc/128, Hc*Bc);
        gemm_bf3_kernel<false,true,false,false,1><<<gov, 256, GEMM_SMEM>>>(
            psh, psl, pvth, pvtl, nullptr,
            nullptr, poh, pol, Tc, Dc, Tc, TT, TD, 0, TD);

        concat_kernel<<<(int)(HBTD/4/256), 256>>>(poh, pol, pcath, pcatl);

        // a = cat @ Wo^T + bo  (fp32 out)
        dim3 gwo(Dc/128, BT/128, 1);
        gemm_bf3_kernel<false,false,true,false,0><<<gwo, 256, GEMM_SMEM>>>(
            pcath, pcatl, pwoh + (long)l*Dc*Hc*Dc, pwol + (long)l*Dc*Hc*Dc, bo + (long)l*Dc,
            pa, nullptr, nullptr, BT, Dc, Hc*Dc, 0, 0, 0, 0);

        add_ln_kernel<<<BT, 256>>>(px, pa, ln1_g + (long)l*Dc, ln1_b + (long)l*Dc, px, pxh, pxl);

        // MLP
        dim3 gm1(DFFc/128, BT/128, 1);
        gemm_bf3_kernel<false,false,true,true,1><<<gm1, 256, GEMM_SMEM>>>(
            pxh, pxl, pw1h + (long)l*DFFc*Dc, pw1l + (long)l*DFFc*Dc, b1 + (long)l*DFFc,
            nullptr, ph1h, ph1l, BT, DFFc, Dc, 0, 0, 0, 0);
        dim3 gm2(Dc/128, BT/128, 1);
        gemm_bf3_kernel<false,false,true,false,0><<<gm2, 256, GEMM_SMEM>>>(
            ph1h, ph1l, pw2h + (long)l*Dc*DFFc, pw2l + (long)l*Dc*DFFc, b2 + (long)l*Dc,
            pa, nullptr, nullptr, BT, Dc, DFFc, 0, 0, 0, 0);

        add_ln_kernel<<<BT, 256>>>(px, pa, ln2_g + (long)l*Dc, ln2_b + (long)l*Dc, px, pxh, pxl);
    }

    // final LN (split out to tmp) + logits (fp32 into d_out)
    add_ln_kernel<<<BT, 256>>>(px, nullptr, lnf_g, lnf_b, pa, ptmph, ptmpl);
    dim3 glog(Vc/128, BT/128, 1);
    gemm_bf3_kernel<false,false,true,false,0><<<glog, 256, GEMM_SMEM>>>(
        ptmph, ptmpl, pwouth, pwoutl, bout,
        out, nullptr, nullptr, BT, Vc, Dc, 0, 0, 0, 0);

    row_loss_kernel<<<BT, 128>>>(out, labels, prl);
    final_loss_kernel<<<1, 256>>>(prl, out + (out_size - 1));
}